// round 4
// baseline (speedup 1.0000x reference)
#include <cuda_runtime.h>

// ---------------------------------------------------------------------------
// Problem constants
// ---------------------------------------------------------------------------
#define P_ 64
#define N_ 2048
#define M1_ 512
#define M2_ 128
#define K_ 32

// Output packing offsets (float32 elements, reference tuple order)
#define XG_OFF      0            // [64,768]
#define POSG_OFF    49152        // [64,3] zeros
#define BATCHG_OFF  49344        // [64]
#define X2_OFF      49408        // [8192,384]
#define Q2_OFF      3195136      // [8192,3]
#define BATCH2_OFF  3219712      // [8192]
#define VMIN_OFF    3227904      // [64,3]
#define DIFF_OFF    3228096      // [64]

typedef unsigned long long u64;

// ---------------------------------------------------------------------------
// Scratch (device globals; no allocations allowed)
// ---------------------------------------------------------------------------
__device__ float g_pn   [P_ * N_ * 3];
__device__ float g_q1   [P_ * M1_ * 3];
__device__ int   g_nidx1[P_ * M1_ * K_];
__device__ int   g_cnt1 [P_ * M1_];
__device__ float g_x1   [P_ * M1_ * 128];
__device__ int   g_nidx2[P_ * M2_ * K_];
__device__ int   g_cnt2 [P_ * M2_];
// mlp2 intermediates: 4096 tiles x 64 rows x 128 i2-pairs (u64 = f32x2)
__device__ u64   g_h2t  [4096 * 64 * 128];
__device__ u64   g_W2a_p[66 * 256];    // K-paired weights for layer1 (131->pad 132)
__device__ u64   g_W2b_p[128 * 384];   // K-paired weights for layer2 (256)

// ---------------------------------------------------------------------------
// f32x2 packed helpers (sm_103a FFMA2 path — PTX-only per SASS_QUICKREF)
// ---------------------------------------------------------------------------
__device__ __forceinline__ u64 ffma2(u64 a, u64 b, u64 c) {
    u64 d;
    asm("fma.rn.f32x2 %0, %1, %2, %3;" : "=l"(d) : "l"(a), "l"(b), "l"(c));
    return d;
}
__device__ __forceinline__ u64 pack2(float x, float y) {
    u64 r;
    asm("mov.b64 %0, {%1, %2};" : "=l"(r) : "f"(x), "f"(y));
    return r;
}
__device__ __forceinline__ float2 unpk(u64 v) {
    float2 r;
    asm("mov.b64 {%0, %1}, %2;" : "=f"(r.x), "=f"(r.y) : "l"(v));
    return r;
}

// ---------------------------------------------------------------------------
// Exact (non-fused) squared distance: ((dx*dx + dy*dy) + dz*dz)
// ---------------------------------------------------------------------------
__device__ __forceinline__ float dist2e(float ax, float ay, float az,
                                        float bx, float by, float bz) {
    float dx = __fsub_rn(ax, bx);
    float dy = __fsub_rn(ay, by);
    float dz = __fsub_rn(az, bz);
    float s  = __fadd_rn(__fmul_rn(dx, dx), __fmul_rn(dy, dy));
    return __fadd_rn(s, __fmul_rn(dz, dz));
}

// ---------------------------------------------------------------------------
// Kernel 1: per-patch normalization + small pass-through outputs + zero xg
// ---------------------------------------------------------------------------
__global__ __launch_bounds__(256) void norm_kernel(const float* __restrict__ pos,
                                                   float* __restrict__ out) {
    int p = blockIdx.x, t = threadIdx.x;
    const float* base = pos + (size_t)p * N_ * 3;

    float mn0 = 3.4e38f, mn1 = 3.4e38f, mn2 = 3.4e38f;
    float mx0 = -3.4e38f, mx1 = -3.4e38f, mx2 = -3.4e38f;
    for (int i = t; i < N_; i += 256) {
        float v0 = base[i * 3 + 0], v1 = base[i * 3 + 1], v2 = base[i * 3 + 2];
        mn0 = fminf(mn0, v0); mx0 = fmaxf(mx0, v0);
        mn1 = fminf(mn1, v1); mx1 = fmaxf(mx1, v1);
        mn2 = fminf(mn2, v2); mx2 = fmaxf(mx2, v2);
    }
#pragma unroll
    for (int o = 16; o; o >>= 1) {
        mn0 = fminf(mn0, __shfl_down_sync(0xffffffffu, mn0, o));
        mn1 = fminf(mn1, __shfl_down_sync(0xffffffffu, mn1, o));
        mn2 = fminf(mn2, __shfl_down_sync(0xffffffffu, mn2, o));
        mx0 = fmaxf(mx0, __shfl_down_sync(0xffffffffu, mx0, o));
        mx1 = fmaxf(mx1, __shfl_down_sync(0xffffffffu, mx1, o));
        mx2 = fmaxf(mx2, __shfl_down_sync(0xffffffffu, mx2, o));
    }
    __shared__ float s6[8][6];
    if ((t & 31) == 0) {
        int w = t >> 5;
        s6[w][0] = mn0; s6[w][1] = mn1; s6[w][2] = mn2;
        s6[w][3] = mx0; s6[w][4] = mx1; s6[w][5] = mx2;
    }
    __syncthreads();
    __shared__ float fin[4];
    if (t == 0) {
        float a0 = s6[0][0], a1 = s6[0][1], a2 = s6[0][2];
        float b0 = s6[0][3], b1 = s6[0][4], b2 = s6[0][5];
        for (int w = 1; w < 8; w++) {
            a0 = fminf(a0, s6[w][0]); a1 = fminf(a1, s6[w][1]); a2 = fminf(a2, s6[w][2]);
            b0 = fmaxf(b0, s6[w][3]); b1 = fmaxf(b1, s6[w][4]); b2 = fmaxf(b2, s6[w][5]);
        }
        float d0 = __fsub_rn(b0, a0), d1 = __fsub_rn(b1, a1), d2 = __fsub_rn(b2, a2);
        float diff = fmaxf(fmaxf(d0, d1), d2);
        fin[0] = a0; fin[1] = a1; fin[2] = a2; fin[3] = diff;
        out[VMIN_OFF + p * 3 + 0] = a0;
        out[VMIN_OFF + p * 3 + 1] = a1;
        out[VMIN_OFF + p * 3 + 2] = a2;
        out[DIFF_OFF + p] = diff;
    }
    __syncthreads();
    float vx = fin[0], vy = fin[1], vz = fin[2], df = fin[3];
    for (int i = t; i < N_; i += 256) {
        float* o3 = g_pn + ((size_t)p * N_ + i) * 3;
        o3[0] = __fdiv_rn(__fsub_rn(base[i * 3 + 0], vx), df);
        o3[1] = __fdiv_rn(__fsub_rn(base[i * 3 + 1], vy), df);
        o3[2] = __fdiv_rn(__fsub_rn(base[i * 3 + 2], vz), df);
    }
    if (t < 3) out[POSG_OFF + p * 3 + t] = 0.0f;
    if (t == 0) out[BATCHG_OFF + p] = (float)p;
    for (int i = t; i < M2_; i += 256) out[BATCH2_OFF + p * M2_ + i] = (float)p;
    for (int i = t; i < 768; i += 256) out[XG_OFF + p * 768 + i] = 0.0f;
}

// ---------------------------------------------------------------------------
// Kernel 2: farthest point sampling (one block per patch, sequential argmax)
// ---------------------------------------------------------------------------
template <int NPTS, int M>
__global__ __launch_bounds__(512) void fps_kernel(int src_sel, float* q_ext) {
    constexpr int T = 512;
    constexpr int U = NPTS / T;
    __shared__ float spx[NPTS], spy[NPTS], spz[NPTS];
    __shared__ unsigned long long wred[16];
    __shared__ int sj;
    int p = blockIdx.x, t = threadIdx.x;
    const float* base = (src_sel ? g_q1 : g_pn) + (size_t)p * NPTS * 3;
    float* q_out = (q_ext ? q_ext : g_q1) + (size_t)p * M * 3;
    for (int i = t; i < NPTS; i += T) {
        spx[i] = base[i * 3 + 0];
        spy[i] = base[i * 3 + 1];
        spz[i] = base[i * 3 + 2];
    }
    __syncthreads();
    float mx[U], my[U], mz[U], d[U];
    float x0 = spx[0], y0 = spy[0], z0 = spz[0];
#pragma unroll
    for (int u = 0; u < U; u++) {
        int i = t + u * T;
        mx[u] = spx[i]; my[u] = spy[i]; mz[u] = spz[i];
        d[u] = dist2e(mx[u], my[u], mz[u], x0, y0, z0);
    }
    if (t == 0) { q_out[0] = x0; q_out[1] = y0; q_out[2] = z0; }
    for (int it = 1; it < M; it++) {
        unsigned long long best = 0ull;
#pragma unroll
        for (int u = 0; u < U; u++) {
            unsigned long long key =
                ((unsigned long long)__float_as_uint(d[u]) << 32) |
                (unsigned)(NPTS - (t + u * T));
            if (key > best) best = key;
        }
#pragma unroll
        for (int o = 16; o; o >>= 1) {
            unsigned long long v = __shfl_down_sync(0xffffffffu, best, o);
            if (v > best) best = v;
        }
        if ((t & 31) == 0) wred[t >> 5] = best;
        __syncthreads();
        if (t < 32) {
            unsigned long long b = (t < 16) ? wred[t] : 0ull;
#pragma unroll
            for (int o = 8; o; o >>= 1) {
                unsigned long long v = __shfl_down_sync(0xffffffffu, b, o);
                if (v > b) b = v;
            }
            if (t == 0) sj = NPTS - (int)(unsigned)(b & 0xffffffffull);
        }
        __syncthreads();
        int j = sj;
        float jx = spx[j], jy = spy[j], jz = spz[j];
        if (t == 0) {
            q_out[it * 3 + 0] = jx; q_out[it * 3 + 1] = jy; q_out[it * 3 + 2] = jz;
        }
#pragma unroll
        for (int u = 0; u < U; u++) {
            float nd = dist2e(mx[u], my[u], mz[u], jx, jy, jz);
            d[u] = fminf(d[u], nd);
        }
    }
}

// ---------------------------------------------------------------------------
// Kernel 3: radius top-K — branchless register top-K (no local memory).
// ---------------------------------------------------------------------------
template <int NPTS>
__global__ void nbr_kernel(int src_sel, const float* __restrict__ q_ext,
                           int nq, float r2, int lvl) {
    __shared__ float spx[NPTS], spy[NPTS], spz[NPTS];
    int p = blockIdx.x, t = threadIdx.x;
    const float* base = (src_sel ? g_q1 : g_pn) + (size_t)p * NPTS * 3;
    const float* q = (q_ext ? q_ext : g_q1);
    int* nidx = lvl ? g_nidx2 : g_nidx1;
    int* ncnt = lvl ? g_cnt2 : g_cnt1;
    for (int i = t; i < NPTS; i += blockDim.x) {
        spx[i] = base[i * 3 + 0];
        spy[i] = base[i * 3 + 1];
        spz[i] = base[i * 3 + 2];
    }
    __syncthreads();
    if (t >= nq) return;
    const float* qq = q + ((size_t)p * nq + t) * 3;
    float qx = qq[0], qy = qq[1], qz = qq[2];

    float da[K_];
    int ia[K_];
#pragma unroll
    for (int k = 0; k < K_; k++) { da[k] = 3.4e38f; ia[k] = 0; }
    int cnt = 0;
    float maxd = 3.4e38f;
    int maxslot = 0;

    for (int j = 0; j < NPTS; j++) {
        float d2 = dist2e(spx[j], spy[j], spz[j], qx, qy, qz);
        if (d2 <= r2) {
            if (cnt < K_) {
#pragma unroll
                for (int k = 0; k < K_; k++)
                    if (k == cnt) { da[k] = d2; ia[k] = j; }
                cnt++;
                if (cnt == K_) {
                    float bd = da[0]; int bj = ia[0]; int bs = 0;
#pragma unroll
                    for (int k = 1; k < K_; k++) {
                        bool g = (da[k] > bd) || (da[k] == bd && ia[k] > bj);
                        if (g) { bd = da[k]; bj = ia[k]; bs = k; }
                    }
                    maxd = bd; maxslot = bs;
                }
            } else if (d2 < maxd) {
#pragma unroll
                for (int k = 0; k < K_; k++)
                    if (k == maxslot) { da[k] = d2; ia[k] = j; }
                float bd = da[0]; int bj = ia[0]; int bs = 0;
#pragma unroll
                for (int k = 1; k < K_; k++) {
                    bool g = (da[k] > bd) || (da[k] == bd && ia[k] > bj);
                    if (g) { bd = da[k]; bj = ia[k]; bs = k; }
                }
                maxd = bd; maxslot = bs;
            }
        }
    }
    int* outp = nidx + ((size_t)p * nq + t) * K_;
#pragma unroll
    for (int k = 0; k < K_; k++) outp[k] = (k < cnt) ? ia[k] : 0;
    ncnt[(size_t)p * nq + t] = cnt;
}

// ---------------------------------------------------------------------------
// Kernel 4: MLP1 (6 -> 64 relu -> 128 relu) + masked warp-max per query
// ---------------------------------------------------------------------------
__global__ __launch_bounds__(256) void mlp1_kernel(const float* __restrict__ W1a,
                                                   const float* __restrict__ b1a,
                                                   const float* __restrict__ W1b,
                                                   const float* __restrict__ b1b) {
    __shared__ __align__(16) float sWa[6 * 64];
    __shared__ __align__(16) float sba[64];
    __shared__ __align__(16) float sWb[64 * 128];
    __shared__ __align__(16) float sbb[128];
    int t = threadIdx.x;
    for (int i = t; i < 6 * 64; i += 256) sWa[i] = W1a[i];
    for (int i = t; i < 64; i += 256) sba[i] = b1a[i];
    for (int i = t; i < 64 * 128; i += 256) sWb[i] = W1b[i];
    for (int i = t; i < 128; i += 256) sbb[i] = b1b[i];
    __syncthreads();

    int gq = blockIdx.x * 8 + (t >> 5);
    int k = t & 31;
    int p = gq >> 9;
    int cnt = g_cnt1[gq];
    bool valid = (k < cnt);
    float f0 = 0, f1 = 0, f2 = 0, f3 = 0, f4 = 0, f5 = 0;
    {
        int j = g_nidx1[(size_t)gq * K_ + k];
        const float* pj = g_pn + ((size_t)p * N_ + j) * 3;
        const float* qc = g_q1 + (size_t)gq * 3;
        f0 = pj[0]; f1 = pj[1]; f2 = pj[2];
        f3 = f0 - qc[0]; f4 = f1 - qc[1]; f5 = f2 - qc[2];
    }
    float h[64];
#pragma unroll
    for (int c = 0; c < 64; c += 4) {
        float4 b4 = *(const float4*)&sba[c];
        float s0 = b4.x, s1 = b4.y, s2 = b4.z, s3 = b4.w;
#pragma unroll
        for (int i = 0; i < 6; i++) {
            float fv = (i == 0) ? f0 : (i == 1) ? f1 : (i == 2) ? f2
                     : (i == 3) ? f3 : (i == 4) ? f4 : f5;
            float4 w = *(const float4*)&sWa[i * 64 + c];
            s0 = fmaf(fv, w.x, s0); s1 = fmaf(fv, w.y, s1);
            s2 = fmaf(fv, w.z, s2); s3 = fmaf(fv, w.w, s3);
        }
        h[c + 0] = fmaxf(s0, 0.f); h[c + 1] = fmaxf(s1, 0.f);
        h[c + 2] = fmaxf(s2, 0.f); h[c + 3] = fmaxf(s3, 0.f);
    }
    float* xo = g_x1 + (size_t)gq * 128;
#pragma unroll 1
    for (int cb = 0; cb < 16; cb++) {
        const ulonglong2* bb = (const ulonglong2*)&sbb[cb * 8];
        ulonglong2 b01 = bb[0], b23 = bb[1];
        u64 a0 = b01.x, a1 = b01.y, a2 = b23.x, a3 = b23.y;
#pragma unroll
        for (int i = 0; i < 64; i++) {
            u64 hv = pack2(h[i], h[i]);
            const ulonglong2* wr = (const ulonglong2*)&sWb[i * 128 + cb * 8];
            ulonglong2 wA = wr[0], wB = wr[1];
            a0 = ffma2(wA.x, hv, a0); a1 = ffma2(wA.y, hv, a1);
            a2 = ffma2(wB.x, hv, a2); a3 = ffma2(wB.y, hv, a3);
        }
        float2 v0 = unpk(a0), v1 = unpk(a1), v2 = unpk(a2), v3 = unpk(a3);
        float r[8] = {v0.x, v0.y, v1.x, v1.y, v2.x, v2.y, v3.x, v3.y};
        float m[8];
#pragma unroll
        for (int e = 0; e < 8; e++) {
            float s = valid ? fmaxf(r[e], 0.f) : 0.f;
            m[e] = __uint_as_float(__reduce_max_sync(0xffffffffu, __float_as_uint(s)));
        }
        if (k == 0) {
            ((float4*)&xo[cb * 8])[0] = make_float4(m[0], m[1], m[2], m[3]);
            ((float4*)&xo[cb * 8])[1] = make_float4(m[4], m[5], m[6], m[7]);
        }
    }
}

// ---------------------------------------------------------------------------
// Kernel 4.5: prepack W2a/W2b into K-paired u64 layout.
//  g_W2a_p[i2*256+c] = (W2a[2*i2][c], W2a[2*i2+1][c])   (i=131 padded 0)
//  g_W2b_p[i2*384+c] = (W2b[2*i2][c], W2b[2*i2+1][c])
// ---------------------------------------------------------------------------
__global__ __launch_bounds__(256) void prepack_kernel(const float* __restrict__ W2a,
                                                      const float* __restrict__ W2b) {
    int t = blockIdx.x * 256 + threadIdx.x;
    if (t < 66 * 256) {
        int i2 = t / 256, c = t - i2 * 256;
        float lo = W2a[(2 * i2) * 256 + c];
        float hi = (2 * i2 + 1 < 131) ? W2a[(2 * i2 + 1) * 256 + c] : 0.f;
        g_W2a_p[t] = pack2(lo, hi);
    }
    if (t < 128 * 384) {
        int i2 = t / 384, c = t - i2 * 384;
        g_W2b_p[t] = pack2(W2b[(2 * i2) * 384 + c], W2b[(2 * i2 + 1) * 384 + c]);
    }
}

// ---------------------------------------------------------------------------
// Kernel 5a: mlp2 layer1 GEMM. rows=(q,k) 64/tile, N=256, K=131 (66 pairs).
// featT2 smem [64 rows][67 pad] u64 K-pairs; thread tile 8 rows x 8 cols;
// acc u64 = (even-i, odd-i) partials. Output h relu'd, stored K-paired
// row-major to g_h2t for layer2.
// ---------------------------------------------------------------------------
__global__ __launch_bounds__(256) void mlp2a_kernel(const float* __restrict__ q2o,
                                                    const float* __restrict__ b2a) {
    __shared__ u64 featT2[64 * 67];
    __shared__ int sj[64];
    __shared__ float sq[6];
    int tile = blockIdx.x, t = threadIdx.x;
    int gr0 = tile * 64;
    int q0 = gr0 >> 5;            // = tile*2
    int p = q0 >> 7;
    if (t < 64) sj[t] = g_nidx2[gr0 + t];
    if (t < 6)  sq[t] = q2o[q0 * 3 + t];
    __syncthreads();
    {
        int row = t & 63, chunk = t >> 6;     // chunk covers i = chunk*32 .. +31
        int j = sj[row];
        const float4* src = (const float4*)&g_x1[((size_t)(p * M1_ + j)) * 128 + chunk * 32];
#pragma unroll
        for (int v = 0; v < 8; v++) {
            float4 f = src[v];
            int i2 = (chunk * 32 + v * 4) >> 1;
            featT2[row * 67 + i2]     = pack2(f.x, f.y);
            featT2[row * 67 + i2 + 1] = pack2(f.z, f.w);
        }
    }
    if (t < 64) {
        int qq = t >> 5;
        int j = sj[t];
        const float* pj = &g_q1[((size_t)(p * M1_ + j)) * 3];
        float a = pj[0] - sq[qq * 3 + 0];
        float b = pj[1] - sq[qq * 3 + 1];
        float c = pj[2] - sq[qq * 3 + 2];
        featT2[t * 67 + 64] = pack2(a, b);
        featT2[t * 67 + 65] = pack2(c, 0.f);
    }
    __syncthreads();
    int ct = t & 31, rt = t >> 5;
    int c0 = ct * 8;
    u64 acc[8][8];
#pragma unroll
    for (int r = 0; r < 8; r++)
#pragma unroll
        for (int c = 0; c < 8; c++) acc[r][c] = 0ull;
#pragma unroll 2
    for (int i2 = 0; i2 < 66; i2++) {
        const ulonglong2* wp = (const ulonglong2*)&g_W2a_p[i2 * 256 + c0];
        ulonglong2 wA = __ldg(&wp[0]), wB = __ldg(&wp[1]),
                   wC = __ldg(&wp[2]), wD = __ldg(&wp[3]);
        u64 w[8] = {wA.x, wA.y, wB.x, wB.y, wC.x, wC.y, wD.x, wD.y};
#pragma unroll
        for (int r = 0; r < 8; r++) {
            u64 f = featT2[(rt * 8 + r) * 67 + i2];
#pragma unroll
            for (int c = 0; c < 8; c++) acc[r][c] = ffma2(f, w[c], acc[r][c]);
        }
    }
    // epilogue: sum lanes + bias, relu, store K-paired (over output channel c)
    float bb[8];
#pragma unroll
    for (int c = 0; c < 8; c++) bb[c] = __ldg(&b2a[c0 + c]);
    u64* dst = &g_h2t[(size_t)tile * 8192];
#pragma unroll
    for (int r = 0; r < 8; r++) {
        int row = rt * 8 + r;
        float h[8];
#pragma unroll
        for (int c = 0; c < 8; c++) {
            float2 v = unpk(acc[r][c]);
            h[c] = fmaxf(v.x + v.y + bb[c], 0.f);
        }
        ulonglong2* d2 = (ulonglong2*)&dst[row * 128 + (c0 >> 1)];
        d2[0] = make_ulonglong2(pack2(h[0], h[1]), pack2(h[2], h[3]));
        d2[1] = make_ulonglong2(pack2(h[4], h[5]), pack2(h[6], h[7]));
    }
}

// ---------------------------------------------------------------------------
// Kernel 5b: mlp2 layer2 GEMM + masked max. rows 64/tile, N=384, K=256 (128
// pairs). hT smem row-major [64][128] u64. 384 threads: 48 ct x 8 rt, thread
// tile 8 rows x 8 cols. Block owns 2 whole queries -> in-block max reduction.
// ---------------------------------------------------------------------------
#define MLP2B_SMEM (64 * 128 * 8)
__global__ __launch_bounds__(384) void mlp2b_kernel(const float* __restrict__ b2b,
                                                    float* __restrict__ out) {
    extern __shared__ u64 hT[];             // [64][128]
    __shared__ float red[8 * 384];
    int tile = blockIdx.x, t = threadIdx.x;
    const ulonglong2* src = (const ulonglong2*)&g_h2t[(size_t)tile * 8192];
    ulonglong2* d2 = (ulonglong2*)hT;
#pragma unroll
    for (int v = 0; v < 11; v++) {
        int e = t + v * 384;
        if (e < 4096) d2[e] = __ldg(&src[e]);
    }
    __syncthreads();
    int ct = t % 48, rt = t / 48;
    int c0 = ct * 8;
    u64 acc[8][8];
#pragma unroll
    for (int r = 0; r < 8; r++)
#pragma unroll
        for (int c = 0; c < 8; c++) acc[r][c] = 0ull;
#pragma unroll 2
    for (int i2 = 0; i2 < 128; i2++) {
        const ulonglong2* wp = (const ulonglong2*)&g_W2b_p[i2 * 384 + c0];
        ulonglong2 wA = __ldg(&wp[0]), wB = __ldg(&wp[1]),
                   wC = __ldg(&wp[2]), wD = __ldg(&wp[3]);
        u64 w[8] = {wA.x, wA.y, wB.x, wB.y, wC.x, wC.y, wD.x, wD.y};
#pragma unroll
        for (int r = 0; r < 8; r++) {
            u64 f = hT[(rt * 8 + r) * 128 + i2];
#pragma unroll
            for (int c = 0; c < 8; c++) acc[r][c] = ffma2(f, w[c], acc[r][c]);
        }
    }
    // epilogue: bias + relu + masked max over this thread's 8 rows
    int q0 = tile * 2;
    int qq = rt >> 2;                 // rows rt*8.. all within one query
    int cnt = g_cnt2[q0 + qq];
#pragma unroll
    for (int c = 0; c < 8; c++) {
        float bc = __ldg(&b2b[c0 + c]);
        float mm = 0.f;
#pragma unroll
        for (int r = 0; r < 8; r++) {
            int k = (rt * 8 + r) & 31;
            float2 v = unpk(acc[r][c]);
            float val = fmaxf(v.x + v.y + bc, 0.f);
            if (k < cnt) mm = fmaxf(mm, val);
        }
        red[rt * 384 + c0 + c] = mm;
    }
    __syncthreads();
    if ((rt & 3) == 0) {
        int q = q0 + (rt >> 2);
#pragma unroll
        for (int c = 0; c < 8; c++) {
            float v = fmaxf(fmaxf(red[rt * 384 + c0 + c], red[(rt + 1) * 384 + c0 + c]),
                            fmaxf(red[(rt + 2) * 384 + c0 + c], red[(rt + 3) * 384 + c0 + c]));
            out[X2_OFF + (size_t)q * 384 + c0 + c] = v;
        }
    }
}

// ---------------------------------------------------------------------------
// Kernel 6: MLP3 (387 -> 512 relu -> 768 relu) + global max pool via atomics
// ---------------------------------------------------------------------------
__global__ __launch_bounds__(256) void mlp3_kernel(const float* __restrict__ W3a,
                                                   const float* __restrict__ b3a,
                                                   const float* __restrict__ W3b,
                                                   const float* __restrict__ b3b,
                                                   float* __restrict__ out) {
    __shared__ __align__(16) float featT[387 * 8];
    __shared__ __align__(16) float hT[512 * 8];
    int b = blockIdx.x, t = threadIdx.x;
    int qbase = b * 8;
    int p = qbase >> 7;
    for (int e = t; e < 8 * 387; e += 256) {
        int qq = e / 387, i = e - qq * 387;
        int q = qbase + qq;
        float v = (i < 384) ? out[X2_OFF + (size_t)q * 384 + i]
                            : out[Q2_OFF + (size_t)q * 3 + (i - 384)];
        featT[i * 8 + qq] = v;
    }
    __syncthreads();
    {
        float bc0 = b3a[t], bc1 = b3a[t + 256];
        u64 s0[4], s1[4];
        u64 p0 = pack2(bc0, bc0), p1 = pack2(bc1, bc1);
#pragma unroll
        for (int m = 0; m < 4; m++) { s0[m] = p0; s1[m] = p1; }
        for (int i = 0; i < 387; i++) {
            float w0f = W3a[i * 512 + t];
            float w1f = W3a[i * 512 + t + 256];
            u64 w0 = pack2(w0f, w0f), w1 = pack2(w1f, w1f);
            const ulonglong2* fr = (const ulonglong2*)&featT[i * 8];
            ulonglong2 fa = fr[0], fb = fr[1];
            s0[0] = ffma2(fa.x, w0, s0[0]); s0[1] = ffma2(fa.y, w0, s0[1]);
            s0[2] = ffma2(fb.x, w0, s0[2]); s0[3] = ffma2(fb.y, w0, s0[3]);
            s1[0] = ffma2(fa.x, w1, s1[0]); s1[1] = ffma2(fa.y, w1, s1[1]);
            s1[2] = ffma2(fb.x, w1, s1[2]); s1[3] = ffma2(fb.y, w1, s1[3]);
        }
        float4* h0 = (float4*)&hT[t * 8];
        float4* h1 = (float4*)&hT[(t + 256) * 8];
        {
            float2 u0 = unpk(s0[0]), u1 = unpk(s0[1]), u2 = unpk(s0[2]), u3 = unpk(s0[3]);
            h0[0] = make_float4(fmaxf(u0.x, 0.f), fmaxf(u0.y, 0.f), fmaxf(u1.x, 0.f), fmaxf(u1.y, 0.f));
            h0[1] = make_float4(fmaxf(u2.x, 0.f), fmaxf(u2.y, 0.f), fmaxf(u3.x, 0.f), fmaxf(u3.y, 0.f));
        }
        {
            float2 u0 = unpk(s1[0]), u1 = unpk(s1[1]), u2 = unpk(s1[2]), u3 = unpk(s1[3]);
            h1[0] = make_float4(fmaxf(u0.x, 0.f), fmaxf(u0.y, 0.f), fmaxf(u1.x, 0.f), fmaxf(u1.y, 0.f));
            h1[1] = make_float4(fmaxf(u2.x, 0.f), fmaxf(u2.y, 0.f), fmaxf(u3.x, 0.f), fmaxf(u3.y, 0.f));
        }
    }
    __syncthreads();
    {
        float bc0 = b3b[t], bc1 = b3b[t + 256], bc2 = b3b[t + 512];
        u64 s0[4], s1[4], s2[4];
        u64 p0 = pack2(bc0, bc0), p1 = pack2(bc1, bc1), p2 = pack2(bc2, bc2);
#pragma unroll
        for (int m = 0; m < 4; m++) { s0[m] = p0; s1[m] = p1; s2[m] = p2; }
        for (int i = 0; i < 512; i++) {
            float w0f = W3b[i * 768 + t];
            float w1f = W3b[i * 768 + t + 256];
            float w2f = W3b[i * 768 + t + 512];
            u64 w0 = pack2(w0f, w0f), w1 = pack2(w1f, w1f), w2 = pack2(w2f, w2f);
            const ulonglong2* hr = (const ulonglong2*)&hT[i * 8];
            ulonglong2 fa = hr[0], fb = hr[1];
            s0[0] = ffma2(fa.x, w0, s0[0]); s0[1] = ffma2(fa.y, w0, s0[1]);
            s0[2] = ffma2(fb.x, w0, s0[2]); s0[3] = ffma2(fb.y, w0, s0[3]);
            s1[0] = ffma2(fa.x, w1, s1[0]); s1[1] = ffma2(fa.y, w1, s1[1]);
            s1[2] = ffma2(fb.x, w1, s1[2]); s1[3] = ffma2(fb.y, w1, s1[3]);
            s2[0] = ffma2(fa.x, w2, s2[0]); s2[1] = ffma2(fa.y, w2, s2[1]);
            s2[2] = ffma2(fb.x, w2, s2[2]); s2[3] = ffma2(fb.y, w2, s2[3]);
        }
        float m0 = 0.f, m1 = 0.f, m2 = 0.f;
#pragma unroll
        for (int m = 0; m < 4; m++) {
            float2 u0 = unpk(s0[m]), u1 = unpk(s1[m]), u2 = unpk(s2[m]);
            m0 = fmaxf(m0, fmaxf(fmaxf(u0.x, 0.f), fmaxf(u0.y, 0.f)));
            m1 = fmaxf(m1, fmaxf(fmaxf(u1.x, 0.f), fmaxf(u1.y, 0.f)));
            m2 = fmaxf(m2, fmaxf(fmaxf(u2.x, 0.f), fmaxf(u2.y, 0.f)));
        }
        atomicMax((unsigned*)&out[XG_OFF + (size_t)p * 768 + t], __float_as_uint(m0));
        atomicMax((unsigned*)&out[XG_OFF + (size_t)p * 768 + t + 256], __float_as_uint(m1));
        atomicMax((unsigned*)&out[XG_OFF + (size_t)p * 768 + t + 512], __float_as_uint(m2));
    }
}

// ---------------------------------------------------------------------------
// Launch
// ---------------------------------------------------------------------------
extern "C" void kernel_launch(void* const* d_in, const int* in_sizes, int n_in,
                              void* d_out, int out_size) {
    const float* pos = (const float*)d_in[0];
    const float* W1a = (const float*)d_in[2];
    const float* b1a = (const float*)d_in[3];
    const float* W1b = (const float*)d_in[4];
    const float* b1b = (const float*)d_in[5];
    const float* W2a = (const float*)d_in[6];
    const float* b2a = (const float*)d_in[7];
    const float* W2b = (const float*)d_in[8];
    const float* b2b = (const float*)d_in[9];
    const float* W3a = (const float*)d_in[10];
    const float* b3a = (const float*)d_in[11];
    const float* W3b = (const float*)d_in[12];
    const float* b3b = (const float*)d_in[13];
    float* out = (float*)d_out;

    const float R1SQ = (float)(0.15 * 0.15);
    const float R2SQ = (float)(0.3 * 0.3);

    static bool attr_set = false;
    if (!attr_set) {
        cudaFuncSetAttribute(mlp2b_kernel, cudaFuncAttributeMaxDynamicSharedMemorySize,
                             MLP2B_SMEM);
        attr_set = true;
    }

    norm_kernel<<<P_, 256>>>(pos, out);
    prepack_kernel<<<192, 256>>>(W2a, W2b);
    fps_kernel<N_, M1_><<<P_, 512>>>(0, nullptr);
    nbr_kernel<N_><<<P_, 512>>>(0, nullptr, M1_, R1SQ, 0);
    mlp1_kernel<<<P_ * M1_ / 8, 256>>>(W1a, b1a, W1b, b1b);
    fps_kernel<M1_, M2_><<<P_, 512>>>(1, out + Q2_OFF);
    nbr_kernel<M1_><<<P_, 128>>>(1, out + Q2_OFF, M2_, R2SQ, 1);
    mlp2a_kernel<<<4096, 256>>>(out + Q2_OFF, b2a);
    mlp2b_kernel<<<4096, 384, MLP2B_SMEM>>>(b2b, out);
    mlp3_kernel<<<P_ * M2_ / 8, 256>>>(W3a, b3a, W3b, b3b, out);
}

// round 5
// speedup vs baseline: 1.0459x; 1.0459x over previous
#include <cuda_runtime.h>

// ---------------------------------------------------------------------------
// Problem constants
// ---------------------------------------------------------------------------
#define P_ 64
#define N_ 2048
#define M1_ 512
#define M2_ 128
#define K_ 32

// Output packing offsets (float32 elements, reference tuple order)
#define XG_OFF      0            // [64,768]
#define POSG_OFF    49152        // [64,3] zeros
#define BATCHG_OFF  49344        // [64]
#define X2_OFF      49408        // [8192,384]
#define Q2_OFF      3195136      // [8192,3]
#define BATCH2_OFF  3219712      // [8192]
#define VMIN_OFF    3227904      // [64,3]
#define DIFF_OFF    3228096      // [64]

typedef unsigned long long u64;

// ---------------------------------------------------------------------------
// Scratch (device globals; no allocations allowed)
// ---------------------------------------------------------------------------
__device__ float g_pn   [P_ * N_ * 3];
__device__ float g_q1   [P_ * M1_ * 3];
__device__ int   g_nidx1[P_ * M1_ * K_];
__device__ int   g_cnt1 [P_ * M1_];
__device__ float g_x1   [P_ * M1_ * 128];
__device__ int   g_nidx2[P_ * M2_ * K_];
__device__ int   g_cnt2 [P_ * M2_];
// mlp2 intermediates: 4096 tiles x 64 rows x 128 i2-pairs (u64 = f32x2)
__device__ u64   g_h2t  [4096 * 64 * 128];
__device__ u64   g_W2a_p[66 * 256];    // K-paired weights layer1 (131 -> pad 132)
__device__ u64   g_W2b_p[128 * 384];   // K-paired weights layer2 (256)

// ---------------------------------------------------------------------------
// f32x2 packed helpers (sm_103a FFMA2 path — PTX-only per SASS_QUICKREF)
// ---------------------------------------------------------------------------
__device__ __forceinline__ u64 ffma2(u64 a, u64 b, u64 c) {
    u64 d;
    asm("fma.rn.f32x2 %0, %1, %2, %3;" : "=l"(d) : "l"(a), "l"(b), "l"(c));
    return d;
}
__device__ __forceinline__ u64 pack2(float x, float y) {
    u64 r;
    asm("mov.b64 %0, {%1, %2};" : "=l"(r) : "f"(x), "f"(y));
    return r;
}
__device__ __forceinline__ float2 unpk(u64 v) {
    float2 r;
    asm("mov.b64 {%0, %1}, %2;" : "=f"(r.x), "=f"(r.y) : "l"(v));
    return r;
}

// ---------------------------------------------------------------------------
// Exact (non-fused) squared distance: ((dx*dx + dy*dy) + dz*dz)
// ---------------------------------------------------------------------------
__device__ __forceinline__ float dist2e(float ax, float ay, float az,
                                        float bx, float by, float bz) {
    float dx = __fsub_rn(ax, bx);
    float dy = __fsub_rn(ay, by);
    float dz = __fsub_rn(az, bz);
    float s  = __fadd_rn(__fmul_rn(dx, dx), __fmul_rn(dy, dy));
    return __fadd_rn(s, __fmul_rn(dz, dz));
}

// ---------------------------------------------------------------------------
// Kernel 1: per-patch normalization + small pass-through outputs + zero xg
// ---------------------------------------------------------------------------
__global__ __launch_bounds__(256) void norm_kernel(const float* __restrict__ pos,
                                                   float* __restrict__ out) {
    int p = blockIdx.x, t = threadIdx.x;
    const float* base = pos + (size_t)p * N_ * 3;

    float mn0 = 3.4e38f, mn1 = 3.4e38f, mn2 = 3.4e38f;
    float mx0 = -3.4e38f, mx1 = -3.4e38f, mx2 = -3.4e38f;
    for (int i = t; i < N_; i += 256) {
        float v0 = base[i * 3 + 0], v1 = base[i * 3 + 1], v2 = base[i * 3 + 2];
        mn0 = fminf(mn0, v0); mx0 = fmaxf(mx0, v0);
        mn1 = fminf(mn1, v1); mx1 = fmaxf(mx1, v1);
        mn2 = fminf(mn2, v2); mx2 = fmaxf(mx2, v2);
    }
#pragma unroll
    for (int o = 16; o; o >>= 1) {
        mn0 = fminf(mn0, __shfl_down_sync(0xffffffffu, mn0, o));
        mn1 = fminf(mn1, __shfl_down_sync(0xffffffffu, mn1, o));
        mn2 = fminf(mn2, __shfl_down_sync(0xffffffffu, mn2, o));
        mx0 = fmaxf(mx0, __shfl_down_sync(0xffffffffu, mx0, o));
        mx1 = fmaxf(mx1, __shfl_down_sync(0xffffffffu, mx1, o));
        mx2 = fmaxf(mx2, __shfl_down_sync(0xffffffffu, mx2, o));
    }
    __shared__ float s6[8][6];
    if ((t & 31) == 0) {
        int w = t >> 5;
        s6[w][0] = mn0; s6[w][1] = mn1; s6[w][2] = mn2;
        s6[w][3] = mx0; s6[w][4] = mx1; s6[w][5] = mx2;
    }
    __syncthreads();
    __shared__ float fin[4];
    if (t == 0) {
        float a0 = s6[0][0], a1 = s6[0][1], a2 = s6[0][2];
        float b0 = s6[0][3], b1 = s6[0][4], b2 = s6[0][5];
        for (int w = 1; w < 8; w++) {
            a0 = fminf(a0, s6[w][0]); a1 = fminf(a1, s6[w][1]); a2 = fminf(a2, s6[w][2]);
            b0 = fmaxf(b0, s6[w][3]); b1 = fmaxf(b1, s6[w][4]); b2 = fmaxf(b2, s6[w][5]);
        }
        float d0 = __fsub_rn(b0, a0), d1 = __fsub_rn(b1, a1), d2 = __fsub_rn(b2, a2);
        float diff = fmaxf(fmaxf(d0, d1), d2);
        fin[0] = a0; fin[1] = a1; fin[2] = a2; fin[3] = diff;
        out[VMIN_OFF + p * 3 + 0] = a0;
        out[VMIN_OFF + p * 3 + 1] = a1;
        out[VMIN_OFF + p * 3 + 2] = a2;
        out[DIFF_OFF + p] = diff;
    }
    __syncthreads();
    float vx = fin[0], vy = fin[1], vz = fin[2], df = fin[3];
    for (int i = t; i < N_; i += 256) {
        float* o3 = g_pn + ((size_t)p * N_ + i) * 3;
        o3[0] = __fdiv_rn(__fsub_rn(base[i * 3 + 0], vx), df);
        o3[1] = __fdiv_rn(__fsub_rn(base[i * 3 + 1], vy), df);
        o3[2] = __fdiv_rn(__fsub_rn(base[i * 3 + 2], vz), df);
    }
    if (t < 3) out[POSG_OFF + p * 3 + t] = 0.0f;
    if (t == 0) out[BATCHG_OFF + p] = (float)p;
    for (int i = t; i < M2_; i += 256) out[BATCH2_OFF + p * M2_ + i] = (float)p;
    for (int i = t; i < 768; i += 256) out[XG_OFF + p * 768 + i] = 0.0f;
}

// ---------------------------------------------------------------------------
// Kernel 2: farthest point sampling (one block per patch, sequential argmax)
// ---------------------------------------------------------------------------
template <int NPTS, int M>
__global__ __launch_bounds__(512) void fps_kernel(int src_sel, float* q_ext) {
    constexpr int T = 512;
    constexpr int U = NPTS / T;
    __shared__ float spx[NPTS], spy[NPTS], spz[NPTS];
    __shared__ unsigned long long wred[16];
    __shared__ int sj;
    int p = blockIdx.x, t = threadIdx.x;
    const float* base = (src_sel ? g_q1 : g_pn) + (size_t)p * NPTS * 3;
    float* q_out = (q_ext ? q_ext : g_q1) + (size_t)p * M * 3;
    for (int i = t; i < NPTS; i += T) {
        spx[i] = base[i * 3 + 0];
        spy[i] = base[i * 3 + 1];
        spz[i] = base[i * 3 + 2];
    }
    __syncthreads();
    float mx[U], my[U], mz[U], d[U];
    float x0 = spx[0], y0 = spy[0], z0 = spz[0];
#pragma unroll
    for (int u = 0; u < U; u++) {
        int i = t + u * T;
        mx[u] = spx[i]; my[u] = spy[i]; mz[u] = spz[i];
        d[u] = dist2e(mx[u], my[u], mz[u], x0, y0, z0);
    }
    if (t == 0) { q_out[0] = x0; q_out[1] = y0; q_out[2] = z0; }
    for (int it = 1; it < M; it++) {
        unsigned long long best = 0ull;
#pragma unroll
        for (int u = 0; u < U; u++) {
            unsigned long long key =
                ((unsigned long long)__float_as_uint(d[u]) << 32) |
                (unsigned)(NPTS - (t + u * T));
            if (key > best) best = key;
        }
#pragma unroll
        for (int o = 16; o; o >>= 1) {
            unsigned long long v = __shfl_down_sync(0xffffffffu, best, o);
            if (v > best) best = v;
        }
        if ((t & 31) == 0) wred[t >> 5] = best;
        __syncthreads();
        if (t < 32) {
            unsigned long long b = (t < 16) ? wred[t] : 0ull;
#pragma unroll
            for (int o = 8; o; o >>= 1) {
                unsigned long long v = __shfl_down_sync(0xffffffffu, b, o);
                if (v > b) b = v;
            }
            if (t == 0) sj = NPTS - (int)(unsigned)(b & 0xffffffffull);
        }
        __syncthreads();
        int j = sj;
        float jx = spx[j], jy = spy[j], jz = spz[j];
        if (t == 0) {
            q_out[it * 3 + 0] = jx; q_out[it * 3 + 1] = jy; q_out[it * 3 + 2] = jz;
        }
#pragma unroll
        for (int u = 0; u < U; u++) {
            float nd = dist2e(mx[u], my[u], mz[u], jx, jy, jz);
            d[u] = fminf(d[u], nd);
        }
    }
}

// ---------------------------------------------------------------------------
// Kernel 3: radius top-K — branchless register top-K (no local memory).
// ---------------------------------------------------------------------------
template <int NPTS>
__global__ void nbr_kernel(int src_sel, const float* __restrict__ q_ext,
                           int nq, float r2, int lvl) {
    __shared__ float spx[NPTS], spy[NPTS], spz[NPTS];
    int p = blockIdx.x, t = threadIdx.x;
    const float* base = (src_sel ? g_q1 : g_pn) + (size_t)p * NPTS * 3;
    const float* q = (q_ext ? q_ext : g_q1);
    int* nidx = lvl ? g_nidx2 : g_nidx1;
    int* ncnt = lvl ? g_cnt2 : g_cnt1;
    for (int i = t; i < NPTS; i += blockDim.x) {
        spx[i] = base[i * 3 + 0];
        spy[i] = base[i * 3 + 1];
        spz[i] = base[i * 3 + 2];
    }
    __syncthreads();
    if (t >= nq) return;
    const float* qq = q + ((size_t)p * nq + t) * 3;
    float qx = qq[0], qy = qq[1], qz = qq[2];

    float da[K_];
    int ia[K_];
#pragma unroll
    for (int k = 0; k < K_; k++) { da[k] = 3.4e38f; ia[k] = 0; }
    int cnt = 0;
    float maxd = 3.4e38f;
    int maxslot = 0;

    for (int j = 0; j < NPTS; j++) {
        float d2 = dist2e(spx[j], spy[j], spz[j], qx, qy, qz);
        if (d2 <= r2) {
            if (cnt < K_) {
#pragma unroll
                for (int k = 0; k < K_; k++)
                    if (k == cnt) { da[k] = d2; ia[k] = j; }
                cnt++;
                if (cnt == K_) {
                    float bd = da[0]; int bj = ia[0]; int bs = 0;
#pragma unroll
                    for (int k = 1; k < K_; k++) {
                        bool g = (da[k] > bd) || (da[k] == bd && ia[k] > bj);
                        if (g) { bd = da[k]; bj = ia[k]; bs = k; }
                    }
                    maxd = bd; maxslot = bs;
                }
            } else if (d2 < maxd) {
#pragma unroll
                for (int k = 0; k < K_; k++)
                    if (k == maxslot) { da[k] = d2; ia[k] = j; }
                float bd = da[0]; int bj = ia[0]; int bs = 0;
#pragma unroll
                for (int k = 1; k < K_; k++) {
                    bool g = (da[k] > bd) || (da[k] == bd && ia[k] > bj);
                    if (g) { bd = da[k]; bj = ia[k]; bs = k; }
                }
                maxd = bd; maxslot = bs;
            }
        }
    }
    int* outp = nidx + ((size_t)p * nq + t) * K_;
#pragma unroll
    for (int k = 0; k < K_; k++) outp[k] = (k < cnt) ? ia[k] : 0;
    ncnt[(size_t)p * nq + t] = cnt;
}

// ---------------------------------------------------------------------------
// Kernel 4: MLP1 (6 -> 64 relu -> 128 relu) + masked warp-max per query
// ---------------------------------------------------------------------------
__global__ __launch_bounds__(256) void mlp1_kernel(const float* __restrict__ W1a,
                                                   const float* __restrict__ b1a,
                                                   const float* __restrict__ W1b,
                                                   const float* __restrict__ b1b) {
    __shared__ __align__(16) float sWa[6 * 64];
    __shared__ __align__(16) float sba[64];
    __shared__ __align__(16) float sWb[64 * 128];
    __shared__ __align__(16) float sbb[128];
    int t = threadIdx.x;
    for (int i = t; i < 6 * 64; i += 256) sWa[i] = W1a[i];
    for (int i = t; i < 64; i += 256) sba[i] = b1a[i];
    for (int i = t; i < 64 * 128; i += 256) sWb[i] = W1b[i];
    for (int i = t; i < 128; i += 256) sbb[i] = b1b[i];
    __syncthreads();

    int gq = blockIdx.x * 8 + (t >> 5);
    int k = t & 31;
    int p = gq >> 9;
    int cnt = g_cnt1[gq];
    bool valid = (k < cnt);
    float f0 = 0, f1 = 0, f2 = 0, f3 = 0, f4 = 0, f5 = 0;
    {
        int j = g_nidx1[(size_t)gq * K_ + k];
        const float* pj = g_pn + ((size_t)p * N_ + j) * 3;
        const float* qc = g_q1 + (size_t)gq * 3;
        f0 = pj[0]; f1 = pj[1]; f2 = pj[2];
        f3 = f0 - qc[0]; f4 = f1 - qc[1]; f5 = f2 - qc[2];
    }
    float h[64];
#pragma unroll
    for (int c = 0; c < 64; c += 4) {
        float4 b4 = *(const float4*)&sba[c];
        float s0 = b4.x, s1 = b4.y, s2 = b4.z, s3 = b4.w;
#pragma unroll
        for (int i = 0; i < 6; i++) {
            float fv = (i == 0) ? f0 : (i == 1) ? f1 : (i == 2) ? f2
                     : (i == 3) ? f3 : (i == 4) ? f4 : f5;
            float4 w = *(const float4*)&sWa[i * 64 + c];
            s0 = fmaf(fv, w.x, s0); s1 = fmaf(fv, w.y, s1);
            s2 = fmaf(fv, w.z, s2); s3 = fmaf(fv, w.w, s3);
        }
        h[c + 0] = fmaxf(s0, 0.f); h[c + 1] = fmaxf(s1, 0.f);
        h[c + 2] = fmaxf(s2, 0.f); h[c + 3] = fmaxf(s3, 0.f);
    }
    float* xo = g_x1 + (size_t)gq * 128;
#pragma unroll 1
    for (int cb = 0; cb < 16; cb++) {
        const ulonglong2* bb = (const ulonglong2*)&sbb[cb * 8];
        ulonglong2 b01 = bb[0], b23 = bb[1];
        u64 a0 = b01.x, a1 = b01.y, a2 = b23.x, a3 = b23.y;
#pragma unroll
        for (int i = 0; i < 64; i++) {
            u64 hv = pack2(h[i], h[i]);
            const ulonglong2* wr = (const ulonglong2*)&sWb[i * 128 + cb * 8];
            ulonglong2 wA = wr[0], wB = wr[1];
            a0 = ffma2(wA.x, hv, a0); a1 = ffma2(wA.y, hv, a1);
            a2 = ffma2(wB.x, hv, a2); a3 = ffma2(wB.y, hv, a3);
        }
        float2 v0 = unpk(a0), v1 = unpk(a1), v2 = unpk(a2), v3 = unpk(a3);
        float r[8] = {v0.x, v0.y, v1.x, v1.y, v2.x, v2.y, v3.x, v3.y};
        float m[8];
#pragma unroll
        for (int e = 0; e < 8; e++) {
            float s = valid ? fmaxf(r[e], 0.f) : 0.f;
            m[e] = __uint_as_float(__reduce_max_sync(0xffffffffu, __float_as_uint(s)));
        }
        if (k == 0) {
            ((float4*)&xo[cb * 8])[0] = make_float4(m[0], m[1], m[2], m[3]);
            ((float4*)&xo[cb * 8])[1] = make_float4(m[4], m[5], m[6], m[7]);
        }
    }
}

// ---------------------------------------------------------------------------
// Kernel 4.5: prepack W2a/W2b into K-paired u64 layout.
// ---------------------------------------------------------------------------
__global__ __launch_bounds__(256) void prepack_kernel(const float* __restrict__ W2a,
                                                      const float* __restrict__ W2b) {
    int t = blockIdx.x * 256 + threadIdx.x;
    if (t < 66 * 256) {
        int i2 = t / 256, c = t - i2 * 256;
        float lo = W2a[(2 * i2) * 256 + c];
        float hi = (2 * i2 + 1 < 131) ? W2a[(2 * i2 + 1) * 256 + c] : 0.f;
        g_W2a_p[t] = pack2(lo, hi);
    }
    if (t < 128 * 384) {
        int i2 = t / 384, c = t - i2 * 384;
        g_W2b_p[t] = pack2(W2b[(2 * i2) * 384 + c], W2b[(2 * i2 + 1) * 384 + c]);
    }
}

// ---------------------------------------------------------------------------
// Kernel 5a: mlp2 layer1 GEMM. 512 threads, block tile 64 rows x 256 cols,
// thread tile 4 rows x 8 cols (32 u64 acc = 64 regs -> NO SPILL).
// K=131 (66 K-pairs). Output relu'd h stored K-paired to g_h2t.
// ---------------------------------------------------------------------------
__global__ __launch_bounds__(512) void mlp2a_kernel(const float* __restrict__ q2o,
                                                    const float* __restrict__ b2a) {
    __shared__ u64 featT2[64 * 67];
    __shared__ int sj[64];
    __shared__ float sq[6];
    int tile = blockIdx.x, t = threadIdx.x;
    int gr0 = tile * 64;
    int q0 = tile * 2;
    int p = q0 >> 7;
    if (t < 64) sj[t] = g_nidx2[gr0 + t];
    if (t < 6)  sq[t] = q2o[q0 * 3 + t];
    __syncthreads();
    {
        int row = t & 63, chunk = t >> 6;     // chunk 0..7, covers 16 i's
        int j = sj[row];
        const float4* src = (const float4*)&g_x1[((size_t)(p * M1_ + j)) * 128 + chunk * 16];
#pragma unroll
        for (int v = 0; v < 4; v++) {
            float4 f = src[v];
            int i2 = (chunk * 16 + v * 4) >> 1;
            featT2[row * 67 + i2]     = pack2(f.x, f.y);
            featT2[row * 67 + i2 + 1] = pack2(f.z, f.w);
        }
    }
    if (t < 64) {
        int qq = t >> 5;
        int j = sj[t];
        const float* pj = &g_q1[((size_t)(p * M1_ + j)) * 3];
        float a = pj[0] - sq[qq * 3 + 0];
        float b = pj[1] - sq[qq * 3 + 1];
        float c = pj[2] - sq[qq * 3 + 2];
        featT2[t * 67 + 64] = pack2(a, b);
        featT2[t * 67 + 65] = pack2(c, 0.f);
    }
    __syncthreads();
    int ct = t & 31, rt = t >> 5;     // ct: 8 cols, rt: 4 rows
    int c0 = ct * 8;
    int r0 = rt * 4;
    u64 acc[4][8];
#pragma unroll
    for (int r = 0; r < 4; r++)
#pragma unroll
        for (int c = 0; c < 8; c++) acc[r][c] = 0ull;
#pragma unroll 2
    for (int i2 = 0; i2 < 66; i2++) {
        const ulonglong2* wp = (const ulonglong2*)&g_W2a_p[i2 * 256 + c0];
        ulonglong2 wA = __ldg(&wp[0]), wB = __ldg(&wp[1]),
                   wC = __ldg(&wp[2]), wD = __ldg(&wp[3]);
        u64 w[8] = {wA.x, wA.y, wB.x, wB.y, wC.x, wC.y, wD.x, wD.y};
#pragma unroll
        for (int r = 0; r < 4; r++) {
            u64 f = featT2[(r0 + r) * 67 + i2];
#pragma unroll
            for (int c = 0; c < 8; c++) acc[r][c] = ffma2(f, w[c], acc[r][c]);
        }
    }
    float bb[8];
#pragma unroll
    for (int c = 0; c < 8; c++) bb[c] = __ldg(&b2a[c0 + c]);
    u64* dst = &g_h2t[(size_t)tile * 8192];
#pragma unroll
    for (int r = 0; r < 4; r++) {
        int row = r0 + r;
        float h[8];
#pragma unroll
        for (int c = 0; c < 8; c++) {
            float2 v = unpk(acc[r][c]);
            h[c] = fmaxf(v.x + v.y + bb[c], 0.f);
        }
        ulonglong2* d2 = (ulonglong2*)&dst[row * 128 + (c0 >> 1)];
        d2[0] = make_ulonglong2(pack2(h[0], h[1]), pack2(h[2], h[3]));
        d2[1] = make_ulonglong2(pack2(h[4], h[5]), pack2(h[6], h[7]));
    }
}

// ---------------------------------------------------------------------------
// Kernel 5b: mlp2 layer2 GEMM + masked max. grid (4096 tiles, 2 col-halves),
// 256 threads, block tile 64 rows x 192 cols, thread tile 4 rows x 12 cols
// (48 u64 acc = 96 regs -> no spill at 256 thr). K=256 (128 K-pairs).
// ---------------------------------------------------------------------------
#define MLP2B_SMEM (64 * 128 * 8)
__global__ __launch_bounds__(256) void mlp2b_kernel(const float* __restrict__ b2b,
                                                    float* __restrict__ out) {
    extern __shared__ u64 hT[];             // [64][128]
    __shared__ float red[16 * 192];
    int tile = blockIdx.x, half = blockIdx.y, t = threadIdx.x;
    const ulonglong2* src = (const ulonglong2*)&g_h2t[(size_t)tile * 8192];
    ulonglong2* d2 = (ulonglong2*)hT;
#pragma unroll
    for (int v = 0; v < 16; v++) d2[t + v * 256] = __ldg(&src[t + v * 256]);
    __syncthreads();
    int ct = t & 15, rt = t >> 4;           // ct: 12 cols, rt: 4 rows
    int c0 = half * 192 + ct * 12;
    int r0 = rt * 4;
    u64 acc[4][12];
#pragma unroll
    for (int r = 0; r < 4; r++)
#pragma unroll
        for (int c = 0; c < 12; c++) acc[r][c] = 0ull;
#pragma unroll 2
    for (int i2 = 0; i2 < 128; i2++) {
        const ulonglong2* wp = (const ulonglong2*)&g_W2b_p[i2 * 384 + c0];
        ulonglong2 wA = __ldg(&wp[0]), wB = __ldg(&wp[1]), wC = __ldg(&wp[2]),
                   wD = __ldg(&wp[3]), wE = __ldg(&wp[4]), wF = __ldg(&wp[5]);
        u64 w[12] = {wA.x, wA.y, wB.x, wB.y, wC.x, wC.y,
                     wD.x, wD.y, wE.x, wE.y, wF.x, wF.y};
#pragma unroll
        for (int r = 0; r < 4; r++) {
            u64 f = hT[(r0 + r) * 128 + i2];
#pragma unroll
            for (int c = 0; c < 12; c++) acc[r][c] = ffma2(f, w[c], acc[r][c]);
        }
    }
    // masked max over this thread's 4 rows (all in one query: rt<8 -> q0)
    int q0 = tile * 2;
    int cnt = g_cnt2[q0 + (rt >> 3)];
#pragma unroll
    for (int c = 0; c < 12; c++) {
        float bc = __ldg(&b2b[c0 + c]);
        float mm = 0.f;
#pragma unroll
        for (int r = 0; r < 4; r++) {
            int k = (r0 + r) & 31;
            float2 v = unpk(acc[r][c]);
            float val = fmaxf(v.x + v.y + bc, 0.f);
            if (k < cnt) mm = fmaxf(mm, val);
        }
        red[rt * 192 + ct * 12 + c] = mm;
    }
    __syncthreads();
    // reduce 8 rt-groups per query; 384 outputs (2 queries x 192 cols)
    for (int e = t; e < 384; e += 256) {
        int qq = e / 192, c = e - qq * 192;
        float m = 0.f;
#pragma unroll
        for (int r = 0; r < 8; r++) m = fmaxf(m, red[(qq * 8 + r) * 192 + c]);
        out[X2_OFF + (size_t)(q0 + qq) * 384 + half * 192 + c] = m;
    }
}

// ---------------------------------------------------------------------------
// Kernel 6: MLP3 (387 -> 512 relu -> 768 relu) + global max pool via atomics
// ---------------------------------------------------------------------------
__global__ __launch_bounds__(256) void mlp3_kernel(const float* __restrict__ W3a,
                                                   const float* __restrict__ b3a,
                                                   const float* __restrict__ W3b,
                                                   const float* __restrict__ b3b,
                                                   float* __restrict__ out) {
    __shared__ __align__(16) float featT[387 * 8];
    __shared__ __align__(16) float hT[512 * 8];
    int b = blockIdx.x, t = threadIdx.x;
    int qbase = b * 8;
    int p = qbase >> 7;
    for (int e = t; e < 8 * 387; e += 256) {
        int qq = e / 387, i = e - qq * 387;
        int q = qbase + qq;
        float v = (i < 384) ? out[X2_OFF + (size_t)q * 384 + i]
                            : out[Q2_OFF + (size_t)q * 3 + (i - 384)];
        featT[i * 8 + qq] = v;
    }
    __syncthreads();
    {
        float bc0 = b3a[t], bc1 = b3a[t + 256];
        u64 s0[4], s1[4];
        u64 p0 = pack2(bc0, bc0), p1 = pack2(bc1, bc1);
#pragma unroll
        for (int m = 0; m < 4; m++) { s0[m] = p0; s1[m] = p1; }
        for (int i = 0; i < 387; i++) {
            float w0f = W3a[i * 512 + t];
            float w1f = W3a[i * 512 + t + 256];
            u64 w0 = pack2(w0f, w0f), w1 = pack2(w1f, w1f);
            const ulonglong2* fr = (const ulonglong2*)&featT[i * 8];
            ulonglong2 fa = fr[0], fb = fr[1];
            s0[0] = ffma2(fa.x, w0, s0[0]); s0[1] = ffma2(fa.y, w0, s0[1]);
            s0[2] = ffma2(fb.x, w0, s0[2]); s0[3] = ffma2(fb.y, w0, s0[3]);
            s1[0] = ffma2(fa.x, w1, s1[0]); s1[1] = ffma2(fa.y, w1, s1[1]);
            s1[2] = ffma2(fb.x, w1, s1[2]); s1[3] = ffma2(fb.y, w1, s1[3]);
        }
        float4* h0 = (float4*)&hT[t * 8];
        float4* h1 = (float4*)&hT[(t + 256) * 8];
        {
            float2 u0 = unpk(s0[0]), u1 = unpk(s0[1]), u2 = unpk(s0[2]), u3 = unpk(s0[3]);
            h0[0] = make_float4(fmaxf(u0.x, 0.f), fmaxf(u0.y, 0.f), fmaxf(u1.x, 0.f), fmaxf(u1.y, 0.f));
            h0[1] = make_float4(fmaxf(u2.x, 0.f), fmaxf(u2.y, 0.f), fmaxf(u3.x, 0.f), fmaxf(u3.y, 0.f));
        }
        {
            float2 u0 = unpk(s1[0]), u1 = unpk(s1[1]), u2 = unpk(s1[2]), u3 = unpk(s1[3]);
            h1[0] = make_float4(fmaxf(u0.x, 0.f), fmaxf(u0.y, 0.f), fmaxf(u1.x, 0.f), fmaxf(u1.y, 0.f));
            h1[1] = make_float4(fmaxf(u2.x, 0.f), fmaxf(u2.y, 0.f), fmaxf(u3.x, 0.f), fmaxf(u3.y, 0.f));
        }
    }
    __syncthreads();
    {
        float bc0 = b3b[t], bc1 = b3b[t + 256], bc2 = b3b[t + 512];
        u64 s0[4], s1[4], s2[4];
        u64 p0 = pack2(bc0, bc0), p1 = pack2(bc1, bc1), p2 = pack2(bc2, bc2);
#pragma unroll
        for (int m = 0; m < 4; m++) { s0[m] = p0; s1[m] = p1; s2[m] = p2; }
        for (int i = 0; i < 512; i++) {
            float w0f = W3b[i * 768 + t];
            float w1f = W3b[i * 768 + t + 256];
            float w2f = W3b[i * 768 + t + 512];
            u64 w0 = pack2(w0f, w0f), w1 = pack2(w1f, w1f), w2 = pack2(w2f, w2f);
            const ulonglong2* hr = (const ulonglong2*)&hT[i * 8];
            ulonglong2 fa = hr[0], fb = hr[1];
            s0[0] = ffma2(fa.x, w0, s0[0]); s0[1] = ffma2(fa.y, w0, s0[1]);
            s0[2] = ffma2(fb.x, w0, s0[2]); s0[3] = ffma2(fb.y, w0, s0[3]);
            s1[0] = ffma2(fa.x, w1, s1[0]); s1[1] = ffma2(fa.y, w1, s1[1]);
            s1[2] = ffma2(fb.x, w1, s1[2]); s1[3] = ffma2(fb.y, w1, s1[3]);
            s2[0] = ffma2(fa.x, w2, s2[0]); s2[1] = ffma2(fa.y, w2, s2[1]);
            s2[2] = ffma2(fb.x, w2, s2[2]); s2[3] = ffma2(fb.y, w2, s2[3]);
        }
        float m0 = 0.f, m1 = 0.f, m2 = 0.f;
#pragma unroll
        for (int m = 0; m < 4; m++) {
            float2 u0 = unpk(s0[m]), u1 = unpk(s1[m]), u2 = unpk(s2[m]);
            m0 = fmaxf(m0, fmaxf(fmaxf(u0.x, 0.f), fmaxf(u0.y, 0.f)));
            m1 = fmaxf(m1, fmaxf(fmaxf(u1.x, 0.f), fmaxf(u1.y, 0.f)));
            m2 = fmaxf(m2, fmaxf(fmaxf(u2.x, 0.f), fmaxf(u2.y, 0.f)));
        }
        atomicMax((unsigned*)&out[XG_OFF + (size_t)p * 768 + t], __float_as_uint(m0));
        atomicMax((unsigned*)&out[XG_OFF + (size_t)p * 768 + t + 256], __float_as_uint(m1));
        atomicMax((unsigned*)&out[XG_OFF + (size_t)p * 768 + t + 512], __float_as_uint(m2));
    }
}

// ---------------------------------------------------------------------------
// Launch
// ---------------------------------------------------------------------------
extern "C" void kernel_launch(void* const* d_in, const int* in_sizes, int n_in,
                              void* d_out, int out_size) {
    const float* pos = (const float*)d_in[0];
    const float* W1a = (const float*)d_in[2];
    const float* b1a = (const float*)d_in[3];
    const float* W1b = (const float*)d_in[4];
    const float* b1b = (const float*)d_in[5];
    const float* W2a = (const float*)d_in[6];
    const float* b2a = (const float*)d_in[7];
    const float* W2b = (const float*)d_in[8];
    const float* b2b = (const float*)d_in[9];
    const float* W3a = (const float*)d_in[10];
    const float* b3a = (const float*)d_in[11];
    const float* W3b = (const float*)d_in[12];
    const float* b3b = (const float*)d_in[13];
    float* out = (float*)d_out;

    const float R1SQ = (float)(0.15 * 0.15);
    const float R2SQ = (float)(0.3 * 0.3);

    static bool attr_set = false;
    if (!attr_set) {
        cudaFuncSetAttribute(mlp2b_kernel, cudaFuncAttributeMaxDynamicSharedMemorySize,
                             MLP2B_SMEM);
        attr_set = true;
    }

    norm_kernel<<<P_, 256>>>(pos, out);
    prepack_kernel<<<192, 256>>>(W2a, W2b);
    fps_kernel<N_, M1_><<<P_, 512>>>(0, nullptr);
    nbr_kernel<N_><<<P_, 512>>>(0, nullptr, M1_, R1SQ, 0);
    mlp1_kernel<<<P_ * M1_ / 8, 256>>>(W1a, b1a, W1b, b1b);
    fps_kernel<M1_, M2_><<<P_, 512>>>(1, out + Q2_OFF);
    nbr_kernel<M1_><<<P_, 128>>>(1, out + Q2_OFF, M2_, R2SQ, 1);
    mlp2a_kernel<<<4096, 512>>>(out + Q2_OFF, b2a);
    dim3 g2b(4096, 2);
    mlp2b_kernel<<<g2b, 256, MLP2B_SMEM>>>(b2b, out);
    mlp3_kernel<<<P_ * M2_ / 8, 256>>>(W3a, b3a, W3b, b3b, out);
}